// round 1
// baseline (speedup 1.0000x reference)
#include <cuda_runtime.h>
#include <math_constants.h>

#define Nn 2
#define Ll 2048
#define Hh 8
#define Ee 64
#define Mm 2048
#define HEADS 16
#define NLH (HEADS*Ll)      // 32768 rows total per tensor

#define NRM   0.3535533905932738f    // 64^-0.25
#define HNRM2 0.0625f                // 0.5 * NRM^2 = 0.5/8
#define RATIO 0.022097086912079608f  // 2048^-0.5
#define KEPS  1e-4f
#define EPSZ  1e-6f

// ---------------- scratch (device globals: alloc-free) ----------------
__device__ float g_Dq[(size_t)HEADS*Ll*Mm];   // 256 MiB: raw dash, then q'
__device__ float g_Dk[(size_t)HEADS*Ll*Mm];   // 256 MiB: raw dash, then k'
__device__ float g_rmax[2][NLH];
__device__ float g_diag[2][NLH];
__device__ float g_ksum[HEADS*Mm];
__device__ float g_kvT[(size_t)HEADS*Mm*Ee];  // kv transposed: [head][m][e]

__device__ __forceinline__ void atomicMaxF(float* addr, float v) {
    int* ia = (int*)addr;
    int old = *ia;
    while (__int_as_float(old) < v) {
        int assumed = old;
        old = atomicCAS(ia, assumed, __float_as_int(v));
        if (old == assumed) break;
    }
}

// ---------------- K0: diag (0.5*nrm^2*|x|^2), init rowmax, zero ksum ----
__global__ __launch_bounds__(256) void k_diag_init(const float* __restrict__ q,
                                                   const float* __restrict__ kk)
{
    int gtid = blockIdx.x * 256 + threadIdx.x;     // 2,097,152 threads total
    if (gtid < HEADS*Mm) g_ksum[gtid] = 0.0f;

    int w    = gtid >> 5;        // warp id = row id over [2*NLH)
    int lane = gtid & 31;
    int which = (w >= NLH) ? 1 : 0;
    int r = which ? (w - NLH) : w;          // r = head*Ll + l
    int head = r >> 11;
    int l    = r & (Ll - 1);
    int n = head >> 3, h = head & 7;
    const float* x = (which ? kk : q) + ((size_t)((n*Ll + l)*Hh + h))*Ee;
    float a = x[lane], b = x[lane + 32];
    float s = a*a + b*b;
    #pragma unroll
    for (int o = 16; o; o >>= 1) s += __shfl_xor_sync(0xffffffffu, s, o);
    if (lane == 0) {
        g_diag[which][r] = HNRM2 * s;
        g_rmax[which][r] = -CUDART_INF_F;
    }
}

// ---------------- K1: featurize GEMM: dash = (x*nrm) @ P^T + rowmax ------
// per head: C[64 l][64 m] tile, K=64. 256 threads, 4x4 per thread.
__global__ __launch_bounds__(256) void k_feat(const float* __restrict__ X,
                                              const float* __restrict__ P,
                                              int which)
{
    __shared__ float As[64][64];   // [l][e]
    __shared__ float Bs[64][68];   // [e][m], padded (transposed from P)

    float* __restrict__ D    = which ? g_Dk : g_Dq;
    float* __restrict__ rmax = g_rmax[which];

    const int head = blockIdx.z;
    const int n = head >> 3, h = head & 7;
    const int l0 = blockIdx.y * 64, m0 = blockIdx.x * 64;
    const int tid = threadIdx.x;
    const int tx = tid & 15, ty = tid >> 4;
    const int rr = tid >> 4;
    const int cc = (tid & 15) * 4;

    #pragma unroll
    for (int p = 0; p < 4; p++) {
        int l = rr + p * 16;
        float4 v = *(const float4*)(X + ((size_t)((n*Ll + l0 + l)*Hh + h))*Ee + cc);
        *(float4*)&As[l][cc] = make_float4(v.x*NRM, v.y*NRM, v.z*NRM, v.w*NRM);
    }
    #pragma unroll
    for (int p = 0; p < 4; p++) {
        int m = rr + p * 16;
        float4 v = *(const float4*)(P + (size_t)(m0 + m)*Ee + cc);
        Bs[cc+0][m] = v.x; Bs[cc+1][m] = v.y; Bs[cc+2][m] = v.z; Bs[cc+3][m] = v.w;
    }
    __syncthreads();

    float acc[4][4] = {};
    #pragma unroll 16
    for (int k = 0; k < 64; k++) {
        float a[4];
        #pragma unroll
        for (int i = 0; i < 4; i++) a[i] = As[ty*4 + i][k];
        float4 b4 = *(const float4*)&Bs[k][tx*4];
        float b[4] = {b4.x, b4.y, b4.z, b4.w};
        #pragma unroll
        for (int i = 0; i < 4; i++)
            #pragma unroll
            for (int j = 0; j < 4; j++)
                acc[i][j] = fmaf(a[i], b[j], acc[i][j]);
    }

    #pragma unroll
    for (int i = 0; i < 4; i++) {
        int l = l0 + ty*4 + i;
        *(float4*)(D + (size_t)(head*Ll + l)*Mm + m0 + tx*4) =
            make_float4(acc[i][0], acc[i][1], acc[i][2], acc[i][3]);
        float rm = fmaxf(fmaxf(acc[i][0], acc[i][1]), fmaxf(acc[i][2], acc[i][3]));
        #pragma unroll
        for (int o = 1; o < 16; o <<= 1)
            rm = fmaxf(rm, __shfl_xor_sync(0xffffffffu, rm, o));
        if (tx == 0) atomicMaxF(&rmax[head*Ll + l], rm);
    }
}

// ---------------- K2: elementwise exp epilogue --------------------------
__global__ __launch_bounds__(256) void k_exp(int which)
{
    float* __restrict__ D = which ? g_Dk : g_Dq;
    const float* __restrict__ rmax = g_rmax[which];
    const float* __restrict__ diag = g_diag[which];
    size_t idx = (size_t)blockIdx.x * 256 + threadIdx.x;  // float4 index
    int row = (int)(idx >> 9);                            // Mm/4 = 512
    float sub = diag[row] + rmax[row];
    float4 v = ((float4*)D)[idx];
    v.x = RATIO * (expf(v.x - sub) + KEPS);
    v.y = RATIO * (expf(v.y - sub) + KEPS);
    v.z = RATIO * (expf(v.z - sub) + KEPS);
    v.w = RATIO * (expf(v.w - sub) + KEPS);
    ((float4*)D)[idx] = v;
}

// ---------------- K3: ksum (column sums of k') ---------------------------
__global__ __launch_bounds__(256) void k_ksum()
{
    int head = blockIdx.z;
    int m = blockIdx.x * 256 + threadIdx.x;
    int s0 = blockIdx.y * 512;
    const float* base = g_Dk + (size_t)(head*Ll + s0)*Mm + m;
    float s = 0.0f;
    #pragma unroll 8
    for (int i = 0; i < 512; i++) s += base[(size_t)i * Mm];
    atomicAdd(&g_ksum[head*Mm + m], s);
}

// ---------------- K4: kv GEMM: kvT[m][e] = sum_s k'[s][m] * v[s][e] ------
__global__ __launch_bounds__(256) void k_kv(const float* __restrict__ V)
{
    __shared__ float As[32][64];  // [s][e]  (v slice)
    __shared__ float Bs[32][64];  // [s][m]  (k' slice)
    const int head = blockIdx.z;
    const int n = head >> 3, h = head & 7;
    const int m0 = blockIdx.x * 64;
    const int tid = threadIdx.x;
    const int tx = tid & 15, ty = tid >> 4;
    const int rr = tid >> 4, cc = (tid & 15) * 4;

    float acc[4][4] = {};   // [e][m]
    for (int s0 = 0; s0 < Ll; s0 += 32) {
        #pragma unroll
        for (int p = 0; p < 2; p++) {
            int s = rr + p * 16;
            *(float4*)&As[s][cc] =
                *(const float4*)(V + ((size_t)((n*Ll + s0 + s)*Hh + h))*Ee + cc);
            *(float4*)&Bs[s][cc] =
                *(const float4*)(g_Dk + (size_t)(head*Ll + s0 + s)*Mm + m0 + cc);
        }
        __syncthreads();
        #pragma unroll
        for (int k = 0; k < 32; k++) {
            float4 a4 = *(const float4*)&As[k][ty*4];
            float4 b4 = *(const float4*)&Bs[k][tx*4];
            float a[4] = {a4.x, a4.y, a4.z, a4.w};
            float b[4] = {b4.x, b4.y, b4.z, b4.w};
            #pragma unroll
            for (int i = 0; i < 4; i++)
                #pragma unroll
                for (int j = 0; j < 4; j++)
                    acc[i][j] = fmaf(a[i], b[j], acc[i][j]);
        }
        __syncthreads();
    }
    #pragma unroll
    for (int j = 0; j < 4; j++) {
        int m = m0 + tx*4 + j;
        *(float4*)(g_kvT + (size_t)(head*Mm + m)*Ee + ty*4) =
            make_float4(acc[0][j], acc[1][j], acc[2][j], acc[3][j]);
    }
}

// ---------------- K5: out = z * q' @ kv^T, z = 1/(q'.ksum + eps) ---------
__global__ __launch_bounds__(256) void k_out(float* __restrict__ out)
{
    __shared__ float As[64][33];  // [l][mk] padded
    __shared__ float Bs[32][64];  // [mk][e]
    __shared__ float Ks[32];
    __shared__ float denS[64];
    const int head = blockIdx.z;
    const int n = head >> 3, h = head & 7;
    const int l0 = blockIdx.y * 64;
    const int tid = threadIdx.x;
    const int tx = tid & 15, ty = tid >> 4;

    float acc[4][4] = {};   // [l][e]
    float den[4] = {0.f, 0.f, 0.f, 0.f};

    for (int m0 = 0; m0 < Mm; m0 += 32) {
        {
            int lr = tid >> 3;            // 0..31
            int mc = (tid & 7) * 4;
            #pragma unroll
            for (int p = 0; p < 2; p++) {
                int l = lr + p * 32;
                float4 v = *(const float4*)(g_Dq + (size_t)(head*Ll + l0 + l)*Mm + m0 + mc);
                As[l][mc+0] = v.x; As[l][mc+1] = v.y; As[l][mc+2] = v.z; As[l][mc+3] = v.w;
            }
        }
        {
            int mr = tid >> 4;
            int ec = (tid & 15) * 4;
            #pragma unroll
            for (int p = 0; p < 2; p++) {
                int mm = mr + p * 16;
                *(float4*)&Bs[mm][ec] =
                    *(const float4*)(g_kvT + (size_t)(head*Mm + m0 + mm)*Ee + ec);
            }
        }
        if (tid < 32) Ks[tid] = g_ksum[head*Mm + m0 + tid];
        __syncthreads();
        #pragma unroll 8
        for (int k = 0; k < 32; k++) {
            float a[4];
            #pragma unroll
            for (int i = 0; i < 4; i++) a[i] = As[ty*4 + i][k];
            float4 b4 = *(const float4*)&Bs[k][tx*4];
            float b[4] = {b4.x, b4.y, b4.z, b4.w};
            #pragma unroll
            for (int i = 0; i < 4; i++)
                #pragma unroll
                for (int j = 0; j < 4; j++)
                    acc[i][j] = fmaf(a[i], b[j], acc[i][j]);
            if (tx == 0) {
                float ks = Ks[k];
                #pragma unroll
                for (int i = 0; i < 4; i++) den[i] = fmaf(a[i], ks, den[i]);
            }
        }
        __syncthreads();
    }
    if (tx == 0) {
        #pragma unroll
        for (int i = 0; i < 4; i++) denS[ty*4 + i] = den[i];
    }
    __syncthreads();
    #pragma unroll
    for (int i = 0; i < 4; i++) {
        int l = l0 + ty*4 + i;
        float z = 1.0f / (denS[ty*4 + i] + EPSZ);
        *(float4*)(out + ((size_t)((n*Ll + l)*Hh + h))*Ee + tx*4) =
            make_float4(acc[i][0]*z, acc[i][1]*z, acc[i][2]*z, acc[i][3]*z);
    }
}

// ---------------- launch ----------------
extern "C" void kernel_launch(void* const* d_in, const int* in_sizes, int n_in,
                              void* d_out, int out_size)
{
    const float* q = (const float*)d_in[0];
    const float* k = (const float*)d_in[1];
    const float* v = (const float*)d_in[2];
    const float* p = (const float*)d_in[3];
    float* out = (float*)d_out;

    k_diag_init<<<8192, 256>>>(q, k);
    k_feat<<<dim3(32, 32, HEADS), 256>>>(q, p, 0);
    k_feat<<<dim3(32, 32, HEADS), 256>>>(k, p, 1);
    k_exp<<<65536, 256>>>(0);
    k_exp<<<65536, 256>>>(1);
    k_ksum<<<dim3(8, 4, HEADS), 256>>>();
    k_kv<<<dim3(32, 1, HEADS), 256>>>(v);
    k_out<<<dim3(1, 32, HEADS), 256>>>(out);
}

// round 3
// speedup vs baseline: 1.3118x; 1.3118x over previous
#include <cuda_runtime.h>
#include <cuda_bf16.h>
#include <mma.h>
#include <math_constants.h>
#include <cstdint>

using namespace nvcuda;

#define Nn 2
#define Ll 2048
#define Hh 8
#define Ee 64
#define Mm 2048
#define HEADS 16
#define NLH (HEADS*Ll)

#define NRM   0.3535533905932738f    // 64^-0.25
#define HNRM2 0.0625f                // 0.5 * NRM^2
#define RATIO 0.022097086912079608f  // 2048^-0.5
#define KEPS  1e-4f
#define EPSZ  1e-6f

// ---------------- scratch ----------------
__device__ float g_Dq[(size_t)HEADS*Ll*Mm];   // raw dash (queries) 256MB
__device__ float g_Dk[(size_t)HEADS*Ll*Mm];   // raw dash (keys)    256MB
__device__ float g_rmax[2][NLH];
__device__ float g_diag[2][NLH];
__device__ float g_ksum[HEADS*Mm];
__device__ float g_kvT[(size_t)HEADS*Ee*Mm];  // kv transposed [head][e][m]

__device__ __forceinline__ void atomicMaxF(float* addr, float v) {
    int* ia = (int*)addr;
    int old = *ia;
    while (__int_as_float(old) < v) {
        int assumed = old;
        old = atomicCAS(ia, assumed, __float_as_int(v));
        if (old == assumed) break;
    }
}

// split fp32 -> bf16 hi + bf16 lo (residual)
__device__ __forceinline__ void split1(float v, __nv_bfloat16& hi, __nv_bfloat16& lo) {
    hi = __float2bfloat16_rn(v);
    lo = __float2bfloat16_rn(v - __bfloat162float(hi));
}
__device__ __forceinline__ void split4pack(const float* v, uint2& hi, uint2& lo) {
    __nv_bfloat16 h[4], l[4];
    #pragma unroll
    for (int i = 0; i < 4; i++) split1(v[i], h[i], l[i]);
    __nv_bfloat162 a = __halves2bfloat162(h[0], h[1]), b = __halves2bfloat162(h[2], h[3]);
    __nv_bfloat162 c = __halves2bfloat162(l[0], l[1]), d = __halves2bfloat162(l[2], l[3]);
    hi.x = *(uint32_t*)&a; hi.y = *(uint32_t*)&b;
    lo.x = *(uint32_t*)&c; lo.y = *(uint32_t*)&d;
}

typedef wmma::fragment<wmma::matrix_a, 16, 16, 16, __nv_bfloat16, wmma::row_major> FragA;
typedef wmma::fragment<wmma::matrix_b, 16, 16, 16, __nv_bfloat16, wmma::col_major> FragB;
typedef wmma::fragment<wmma::accumulator, 16, 16, 16, float> FragC;

// ================== K0: diag + rowmax init ==================
__global__ __launch_bounds__(256) void k_init(const float* __restrict__ q,
                                              const float* __restrict__ kk)
{
    int g = blockIdx.x * 256 + threadIdx.x;
    int w = g >> 5, lane = g & 31;
    int which = (w >= NLH) ? 1 : 0;
    int r = which ? (w - NLH) : w;
    int head = r >> 11, l = r & (Ll - 1);
    int n = head >> 3, h = head & 7;
    const float* x = (which ? kk : q) + ((size_t)((n*Ll + l)*Hh + h))*Ee;
    float a = x[lane], b = x[lane + 32];
    float s = a*a + b*b;
    #pragma unroll
    for (int o = 16; o; o >>= 1) s += __shfl_xor_sync(0xffffffffu, s, o);
    if (lane == 0) {
        g_diag[which][r] = HNRM2 * s;
        g_rmax[which][r] = -CUDART_INF_F;
    }
}

// ================== K1: featurize: dash = (x*NRM) @ P^T, raw out + rowmax ==
// block tile: 128 l x 128 m, K = 64. 8 warps, warp tile 32l x 64m.
#define FK_LD 72
#define F_SMEM 73728
__global__ __launch_bounds__(256, 2) void k_feat(const float* __restrict__ X,
                                                 const float* __restrict__ P,
                                                 int which)
{
    extern __shared__ char smem[];
    __nv_bfloat16* Ahi = (__nv_bfloat16*)(smem);
    __nv_bfloat16* Alo = (__nv_bfloat16*)(smem + 18432);
    __nv_bfloat16* Bhi = (__nv_bfloat16*)(smem + 36864);
    __nv_bfloat16* Blo = (__nv_bfloat16*)(smem + 55296);
    float* stage = (float*)smem;          // reuse after MMA, ld=132

    float* __restrict__ Dash = which ? g_Dk : g_Dq;
    float* __restrict__ rmax = g_rmax[which];

    const int head = blockIdx.z, n = head >> 3, h = head & 7;
    const int l0 = blockIdx.y * 128, m0 = blockIdx.x * 128;
    const int tid = threadIdx.x, wid = tid >> 5, lane = tid & 31;

    // load + split A (x*NRM) and B (P rows)
    {
        int row = tid >> 1;
        int colb = (tid & 1) * 32;
        const float* srcA = X + ((size_t)((n*Ll + l0 + row)*Hh + h))*Ee + colb;
        const float* srcB = P + (size_t)(m0 + row)*Ee + colb;
        #pragma unroll
        for (int j = 0; j < 8; j++) {
            float4 va = *(const float4*)(srcA + j*4);
            float av[4] = {va.x*NRM, va.y*NRM, va.z*NRM, va.w*NRM};
            uint2 hi, lo; split4pack(av, hi, lo);
            int off = row*FK_LD + colb + j*4;
            *(uint2*)&Ahi[off] = hi; *(uint2*)&Alo[off] = lo;
            float4 vb = *(const float4*)(srcB + j*4);
            float bv[4] = {vb.x, vb.y, vb.z, vb.w};
            split4pack(bv, hi, lo);
            *(uint2*)&Bhi[off] = hi; *(uint2*)&Blo[off] = lo;
        }
    }
    __syncthreads();

    const int warp_l = (wid & 3) * 32, warp_m = (wid >> 2) * 64;
    FragC c[2][4];
    #pragma unroll
    for (int i = 0; i < 2; i++)
        #pragma unroll
        for (int j = 0; j < 4; j++) wmma::fill_fragment(c[i][j], 0.0f);

    #pragma unroll
    for (int k = 0; k < 4; k++) {
        FragA ahi[2], alo[2];
        #pragma unroll
        for (int i = 0; i < 2; i++) {
            wmma::load_matrix_sync(ahi[i], Ahi + (warp_l + i*16)*FK_LD + k*16, FK_LD);
            wmma::load_matrix_sync(alo[i], Alo + (warp_l + i*16)*FK_LD + k*16, FK_LD);
        }
        #pragma unroll
        for (int j = 0; j < 4; j++) {
            FragB bhi, blo;
            wmma::load_matrix_sync(bhi, Bhi + k*16 + (warp_m + j*16)*FK_LD, FK_LD);
            wmma::load_matrix_sync(blo, Blo + k*16 + (warp_m + j*16)*FK_LD, FK_LD);
            #pragma unroll
            for (int i = 0; i < 2; i++) {
                wmma::mma_sync(c[i][j], ahi[i], bhi, c[i][j]);
                wmma::mma_sync(c[i][j], ahi[i], blo, c[i][j]);
                wmma::mma_sync(c[i][j], alo[i], bhi, c[i][j]);
            }
        }
    }
    __syncthreads();
    #pragma unroll
    for (int i = 0; i < 2; i++)
        #pragma unroll
        for (int j = 0; j < 4; j++)
            wmma::store_matrix_sync(stage + (warp_l + i*16)*132 + warp_m + j*16,
                                    c[i][j], 132, wmma::mem_row_major);
    __syncthreads();

    // coalesced store + rowmax (one row per warp-iteration)
    #pragma unroll
    for (int r = 0; r < 16; r++) {
        int row = wid * 16 + r;
        float4 v = *(const float4*)&stage[row*132 + lane*4];
        *(float4*)(Dash + (size_t)(head*Ll + l0 + row)*Mm + m0 + lane*4) = v;
        float rm = fmaxf(fmaxf(v.x, v.y), fmaxf(v.z, v.w));
        #pragma unroll
        for (int o = 16; o; o >>= 1) rm = fmaxf(rm, __shfl_xor_sync(0xffffffffu, rm, o));
        if (lane == 0) atomicMaxF(&rmax[head*Ll + l0 + row], rm);
    }
}

// ================== K2: kv = k'^T @ v  (exp + ksum fused) ==================
// per (head, m-tile 128): C[128m x 64e], K = 2048 s in chunks of 64.
#define KV_LD 72
#define KV_SMEM 55808
__global__ __launch_bounds__(256, 2) void k_kv(const float* __restrict__ V)
{
    extern __shared__ char smem[];
    __nv_bfloat16* Ahi = (__nv_bfloat16*)(smem);             // [128m][72] (s in cols)
    __nv_bfloat16* Alo = (__nv_bfloat16*)(smem + 18432);
    __nv_bfloat16* Bhi = (__nv_bfloat16*)(smem + 36864);     // [64e][72]
    __nv_bfloat16* Blo = (__nv_bfloat16*)(smem + 46080);
    float* KS = (float*)(smem + 55296);
    float* stage = (float*)smem;                             // reuse, col-major ld=132

    const int head = blockIdx.y, n = head >> 3, h = head & 7;
    const int m0 = blockIdx.x * 128;
    const int tid = threadIdx.x, wid = tid >> 5;

    if (tid < 128) KS[tid] = 0.0f;

    const int mA = tid & 127, sgA = (tid >> 7) * 32;     // A gen: 1 m-col, 32 s-rows
    const int eB = tid & 63,  sgB = (tid >> 6) * 16;     // B gen: 1 e-col, 16 s-rows
    const int warp_m = (wid & 3) * 32, warp_e = (wid >> 2) * 32;

    FragC c[2][2];
    #pragma unroll
    for (int i = 0; i < 2; i++)
        #pragma unroll
        for (int j = 0; j < 2; j++) wmma::fill_fragment(c[i][j], 0.0f);

    float ksp = 0.0f;
    __syncthreads();

    for (int st = 0; st < 32; st++) {
        const int s0 = st * 64;
        // A: k' transposed into [m][s]
        {
            const float* dk = g_Dk + (size_t)(head*Ll + s0 + sgA)*Mm + m0 + mA;
            const float* dg = &g_diag[1][head*Ll + s0 + sgA];
            const float* rx = &g_rmax[1][head*Ll + s0 + sgA];
            #pragma unroll
            for (int g = 0; g < 8; g++) {
                float vals[4];
                #pragma unroll
                for (int i = 0; i < 4; i++) {
                    int s = g*4 + i;
                    float sub = dg[s] + rx[s];
                    float d = dk[(size_t)s * Mm];
                    float kk = RATIO * (__expf(d - sub) + KEPS);
                    ksp += kk;
                    vals[i] = kk;
                }
                uint2 hi, lo; split4pack(vals, hi, lo);
                int off = mA*KV_LD + sgA + g*4;
                *(uint2*)&Ahi[off] = hi; *(uint2*)&Alo[off] = lo;
            }
        }
        // B: v transposed into [e][s]
        {
            const float* vp = V + ((size_t)((n*Ll + s0 + sgB)*Hh + h))*Ee + eB;
            #pragma unroll
            for (int g = 0; g < 4; g++) {
                float vals[4];
                #pragma unroll
                for (int i = 0; i < 4; i++)
                    vals[i] = vp[(size_t)(g*4 + i) * (Hh*Ee)];
                uint2 hi, lo; split4pack(vals, hi, lo);
                int off = eB*KV_LD + sgB + g*4;
                *(uint2*)&Bhi[off] = hi; *(uint2*)&Blo[off] = lo;
            }
        }
        __syncthreads();
        #pragma unroll
        for (int k = 0; k < 4; k++) {
            FragA ahi[2], alo[2];
            #pragma unroll
            for (int i = 0; i < 2; i++) {
                wmma::load_matrix_sync(ahi[i], Ahi + (warp_m + i*16)*KV_LD + k*16, KV_LD);
                wmma::load_matrix_sync(alo[i], Alo + (warp_m + i*16)*KV_LD + k*16, KV_LD);
            }
            #pragma unroll
            for (int j = 0; j < 2; j++) {
                FragB bhi, blo;
                wmma::load_matrix_sync(bhi, Bhi + k*16 + (warp_e + j*16)*KV_LD, KV_LD);
                wmma::load_matrix_sync(blo, Blo + k*16 + (warp_e + j*16)*KV_LD, KV_LD);
                #pragma unroll
                for (int i = 0; i < 2; i++) {
                    wmma::mma_sync(c[i][j], ahi[i], bhi, c[i][j]);
                    wmma::mma_sync(c[i][j], ahi[i], blo, c[i][j]);
                    wmma::mma_sync(c[i][j], alo[i], bhi, c[i][j]);
                }
            }
        }
        __syncthreads();
    }

    atomicAdd(&KS[mA], ksp);
    // stage C as col-major [e][m] for coalesced kvT store
    #pragma unroll
    for (int i = 0; i < 2; i++)
        #pragma unroll
        for (int j = 0; j < 2; j++)
            wmma::store_matrix_sync(stage + (warp_m + i*16) + (warp_e + j*16)*132,
                                    c[i][j], 132, wmma::mem_col_major);
    __syncthreads();
    if (tid < 128) g_ksum[head*Mm + m0 + tid] = KS[tid];
    {
        int e = tid >> 2, mo = (tid & 3) * 32;
        float* dst = g_kvT + (size_t)(head*Ee + e)*Mm + m0 + mo;
        const float* src = stage + e*132 + mo;
        #pragma unroll
        for (int j = 0; j < 8; j++)
            *(float4*)(dst + j*4) = *(const float4*)(src + j*4);
    }
}

// ================== K3: out = z * q' @ kv^T (exp + denom fused) ============
#define O_LD 72
#define O_SMEM 56064
__global__ __launch_bounds__(256, 2) void k_out(float* __restrict__ out)
{
    extern __shared__ char smem[];
    __nv_bfloat16* Ahi = (__nv_bfloat16*)(smem);             // [128l][72] (m cols)
    __nv_bfloat16* Alo = (__nv_bfloat16*)(smem + 18432);
    __nv_bfloat16* Bhi = (__nv_bfloat16*)(smem + 36864);     // [64e][72] (m cols)
    __nv_bfloat16* Blo = (__nv_bfloat16*)(smem + 46080);
    float* KSB = (float*)(smem + 55296);
    float* DEN = (float*)(smem + 55552);
    float* stage = (float*)smem;                             // reuse, ld=68

    const int head = blockIdx.y, n = head >> 3, h = head & 7;
    const int l0 = blockIdx.x * 128;
    const int tid = threadIdx.x, wid = tid >> 5;

    if (tid < 128) DEN[tid] = 0.0f;

    const int lA = tid >> 1, mcA = (tid & 1) * 32;
    const int eB = tid >> 2, mcB = (tid & 3) * 16;
    const int warp_l = (wid & 3) * 32, warp_e = (wid >> 2) * 32;

    const int grA = head*Ll + l0 + lA;
    const float subA = g_diag[0][grA] + g_rmax[0][grA];

    FragC c[2][2];
    #pragma unroll
    for (int i = 0; i < 2; i++)
        #pragma unroll
        for (int j = 0; j < 2; j++) wmma::fill_fragment(c[i][j], 0.0f);
    __syncthreads();

    for (int mt = 0; mt < 32; mt++) {
        const int m0 = mt * 64;
        if (tid < 64) KSB[tid] = g_ksum[head*Mm + m0 + tid];
        __syncthreads();
        // A: q' natural [l][m]
        {
            const float* dq = g_Dq + (size_t)grA*Mm + m0 + mcA;
            float ds = 0.0f;
            #pragma unroll
            for (int j = 0; j < 8; j++) {
                float4 d = *(const float4*)(dq + j*4);
                float qv[4];
                qv[0] = RATIO * (__expf(d.x - subA) + KEPS);
                qv[1] = RATIO * (__expf(d.y - subA) + KEPS);
                qv[2] = RATIO * (__expf(d.z - subA) + KEPS);
                qv[3] = RATIO * (__expf(d.w - subA) + KEPS);
                const float* ks = KSB + mcA + j*4;
                ds += qv[0]*ks[0] + qv[1]*ks[1] + qv[2]*ks[2] + qv[3]*ks[3];
                uint2 hi, lo; split4pack(qv, hi, lo);
                int off = lA*O_LD + mcA + j*4;
                *(uint2*)&Ahi[off] = hi; *(uint2*)&Alo[off] = lo;
            }
            atomicAdd(&DEN[lA], ds);
        }
        // B: kvT natural [e][m]
        {
            const float* kv = g_kvT + (size_t)(head*Ee + eB)*Mm + m0 + mcB;
            #pragma unroll
            for (int j = 0; j < 4; j++) {
                float4 d = *(const float4*)(kv + j*4);
                float vv[4] = {d.x, d.y, d.z, d.w};
                uint2 hi, lo; split4pack(vv, hi, lo);
                int off = eB*O_LD + mcB + j*4;
                *(uint2*)&Bhi[off] = hi; *(uint2*)&Blo[off] = lo;
            }
        }
        __syncthreads();
        #pragma unroll
        for (int k = 0; k < 4; k++) {
            FragA ahi[2], alo[2];
            #pragma unroll
            for (int i = 0; i < 2; i++) {
                wmma::load_matrix_sync(ahi[i], Ahi + (warp_l + i*16)*O_LD + k*16, O_LD);
                wmma::load_matrix_sync(alo[i], Alo + (warp_l + i*16)*O_LD + k*16, O_LD);
            }
            #pragma unroll
            for (int j = 0; j < 2; j++) {
                FragB bhi, blo;
                wmma::load_matrix_sync(bhi, Bhi + k*16 + (warp_e + j*16)*O_LD, O_LD);
                wmma::load_matrix_sync(blo, Blo + k*16 + (warp_e + j*16)*O_LD, O_LD);
                #pragma unroll
                for (int i = 0; i < 2; i++) {
                    wmma::mma_sync(c[i][j], ahi[i], bhi, c[i][j]);
                    wmma::mma_sync(c[i][j], ahi[i], blo, c[i][j]);
                    wmma::mma_sync(c[i][j], alo[i], bhi, c[i][j]);
                }
            }
        }
        __syncthreads();
    }

    // epilogue: stage, z-scale, store
    #pragma unroll
    for (int i = 0; i < 2; i++)
        #pragma unroll
        for (int j = 0; j < 2; j++)
            wmma::store_matrix_sync(stage + (warp_l + i*16)*68 + warp_e + j*16,
                                    c[i][j], 68, wmma::mem_row_major);
    __syncthreads();
    {
        int l = tid >> 1, ec = (tid & 1) * 32;
        float z = 1.0f / (DEN[l] + EPSZ);
        float* dst = out + ((size_t)((n*Ll + l0 + l)*Hh + h))*Ee + ec;
        const float* src = stage + l*68 + ec;
        #pragma unroll
        for (int j = 0; j < 8; j++) {
            float4 v = *(const float4*)(src + j*4);
            *(float4*)(dst + j*4) = make_float4(v.x*z, v.y*z, v.z*z, v.w*z);
        }
    }
}

// ================== launch ==================
extern "C" void kernel_launch(void* const* d_in, const int* in_sizes, int n_in,
                              void* d_out, int out_size)
{
    const float* q = (const float*)d_in[0];
    const float* k = (const float*)d_in[1];
    const float* v = (const float*)d_in[2];
    const float* p = (const float*)d_in[3];
    float* out = (float*)d_out;

    cudaFuncSetAttribute(k_feat, cudaFuncAttributeMaxDynamicSharedMemorySize, F_SMEM);
    cudaFuncSetAttribute(k_kv,   cudaFuncAttributeMaxDynamicSharedMemorySize, KV_SMEM);
    cudaFuncSetAttribute(k_out,  cudaFuncAttributeMaxDynamicSharedMemorySize, O_SMEM);

    k_init<<<8192, 256>>>(q, k);
    k_feat<<<dim3(16, 16, HEADS), 256, F_SMEM>>>(q, p, 0);
    k_feat<<<dim3(16, 16, HEADS), 256, F_SMEM>>>(k, p, 1);
    k_kv<<<dim3(16, HEADS), 256, KV_SMEM>>>(v);
    k_out<<<dim3(16, HEADS), 256, O_SMEM>>>(out);
}